// round 4
// baseline (speedup 1.0000x reference)
#include <cuda_runtime.h>
#include <math.h>

// Diffusion: out = expm(-max(t,1e-8) * L) @ x,  L = graph Laplacian (sparse, ~32 nnz/row)
// Method: Chebyshev expansion of e^{-t*lambda} on [0, lambda_ub] applied to the
// block x via sparse matvecs in fp32. lambda_ub = 2*max(diag) (Gershgorin).
// Coefficients + truncation degree computed on-device (fp64 DCT), so the
// fixed launch sequence (graph-capturable) adapts its active work to the data.

#define NN   2048
#define DD   512
#define ELLW 128          // max off-diagonal nnz per row (mean ~32, huge margin)
#define MMAX 48           // highest Chebyshev degree available
#define NQ   256          // quadrature nodes for coefficient DCT

// -------- device-global scratch (no allocations allowed) --------
__device__ int   g_cnt[NN];
__device__ float g_diag[NN];
__device__ int   g_col[NN * ELLW];
__device__ float g_val[NN * ELLW];
__device__ float g_coef[MMAX + 1];
__device__ float g_a;     // 4 / lambda_ub
__device__ int   g_deg;   // truncation degree (data dependent)
__device__ float g_T1[NN * DD];   // Chebyshev vector, odd degrees
__device__ float g_T2[NN * DD];   // Chebyshev vector, even degrees

__device__ __forceinline__ float4 f4_load(const float* p) {
    return *reinterpret_cast<const float4*>(p);
}
__device__ __forceinline__ void f4_store(float* p, float4 v) {
    *reinterpret_cast<float4*>(p) = v;
}

// ---------------------------------------------------------------------------
// 1) Extract sparse structure from dense L. One block per row, 256 threads,
//    each thread scans 8 contiguous columns; deterministic ordered compaction
//    via an in-block inclusive scan.
// ---------------------------------------------------------------------------
__global__ void __launch_bounds__(256) prep_kernel(const float* __restrict__ L) {
    int row = blockIdx.x;
    int t   = threadIdx.x;
    const float* Lr = L + (size_t)row * NN;

    int   cols[8];
    float vals[8];
    int   cnt  = 0;
    float dval = 0.f;
    int base = t * 8;
#pragma unroll
    for (int k = 0; k < 8; k++) {
        int c = base + k;
        float v = Lr[c];
        if (c == row) {
            dval = v;
        } else if (v != 0.f) {
            cols[cnt] = c;
            vals[cnt] = -v;   // store A_ij = -L_ij  (positive weight)
            cnt++;
        }
    }

    __shared__ int s_scan[256];
    s_scan[t] = cnt;
    __syncthreads();
    for (int off = 1; off < 256; off <<= 1) {
        int add = (t >= off) ? s_scan[t - off] : 0;
        __syncthreads();
        s_scan[t] += add;
        __syncthreads();
    }
    int offset = s_scan[t] - cnt;
    int total  = s_scan[255];

    for (int k = 0; k < cnt; k++) {
        int idx = offset + k;
        if (idx < ELLW) {
            g_col[row * ELLW + idx] = cols[k];
            g_val[row * ELLW + idx] = vals[k];
        }
    }
    if ((row >> 3) == t) g_diag[row] = dval;   // thread owning the diagonal column
    if (t == 0) g_cnt[row] = (total < ELLW) ? total : ELLW;
}

// ---------------------------------------------------------------------------
// 2) Chebyshev coefficients of g(s) = exp(-z*(s+1)), z = t*lambda_ub/2,
//    via 256-node DCT in fp64. Also picks truncation degree g_deg with
//    tail-sum tolerance 1e-6 (|T_k| <= 1 so tail-sum bounds the error).
// ---------------------------------------------------------------------------
__global__ void __launch_bounds__(NQ) coeff_kernel(const float* __restrict__ t_in) {
    int t = threadIdx.x;

    // max weighted degree -> Gershgorin bound lambda_ub = 2*maxdeg
    __shared__ float s_max[NQ];
    float m = 0.f;
    for (int i = t; i < NN; i += NQ) m = fmaxf(m, g_diag[i]);
    s_max[t] = m;
    __syncthreads();
    for (int off = NQ / 2; off; off >>= 1) {
        if (t < off) s_max[t] = fmaxf(s_max[t], s_max[t + off]);
        __syncthreads();
    }
    double lub = 2.0 * (double)s_max[0];
    if (lub < 1e-12) lub = 1e-12;

    double tt = (double)fmaxf(t_in[0], 1e-8f);
    double z  = 0.5 * tt * lub;

    // quadrature node value (one per thread)
    const double PI = 3.14159265358979323846;
    double theta = PI * ((double)t + 0.5) / (double)NQ;
    double fj = exp(-z * (cos(theta) + 1.0));

    __shared__ double s_red[NQ];
    __shared__ double s_c[MMAX + 1];
    for (int k = 0; k <= MMAX; k++) {
        s_red[t] = fj * cos((double)k * theta);
        __syncthreads();
        for (int off = NQ / 2; off; off >>= 1) {
            if (t < off) s_red[t] += s_red[t + off];
            __syncthreads();
        }
        if (t == 0) {
            double c = (2.0 / (double)NQ) * s_red[0];
            if (k == 0) c *= 0.5;
            s_c[k] = c;
        }
        __syncthreads();
    }

    if (t == 0) {
        double tail = 0.0;
        int deg = 1;
        for (int k = MMAX; k >= 2; k--) {
            tail += fabs(s_c[k]);
            if (tail > 1e-6) { deg = k; break; }
        }
        g_deg = deg;
        g_a   = (float)(4.0 / lub);
        for (int k = 0; k <= MMAX; k++) g_coef[k] = (float)s_c[k];
    }
}

// ---------------------------------------------------------------------------
// Fused sparse matvec core: acc = diag*y_row - sum_j val_j * Y[col_j, ch..ch+3]
// ---------------------------------------------------------------------------
__device__ __forceinline__ void spmv_row(const float* __restrict__ Y, int ch,
                                         const int* s_col, const float* s_val,
                                         int cnt, float d, float4 yrow,
                                         float& ax, float& ay, float& az, float& aw) {
    ax = d * yrow.x; ay = d * yrow.y; az = d * yrow.z; aw = d * yrow.w;
    int k = 0;
    for (; k + 4 <= cnt; k += 4) {
        int   c0 = s_col[k],   c1 = s_col[k+1], c2 = s_col[k+2], c3 = s_col[k+3];
        float v0 = s_val[k],   v1 = s_val[k+1], v2 = s_val[k+2], v3 = s_val[k+3];
        float4 g0 = f4_load(Y + (((size_t)c0) << 9) + ch);
        float4 g1 = f4_load(Y + (((size_t)c1) << 9) + ch);
        float4 g2 = f4_load(Y + (((size_t)c2) << 9) + ch);
        float4 g3 = f4_load(Y + (((size_t)c3) << 9) + ch);
        ax -= v0 * g0.x; ay -= v0 * g0.y; az -= v0 * g0.z; aw -= v0 * g0.w;
        ax -= v1 * g1.x; ay -= v1 * g1.y; az -= v1 * g1.z; aw -= v1 * g1.w;
        ax -= v2 * g2.x; ay -= v2 * g2.y; az -= v2 * g2.z; aw -= v2 * g2.w;
        ax -= v3 * g3.x; ay -= v3 * g3.y; az -= v3 * g3.z; aw -= v3 * g3.w;
    }
    for (; k < cnt; k++) {
        int   c = s_col[k];
        float v = s_val[k];
        float4 g = f4_load(Y + (((size_t)c) << 9) + ch);
        ax -= v * g.x; ay -= v * g.y; az -= v * g.z; aw -= v * g.w;
    }
}

// ---------------------------------------------------------------------------
// 3) Init: T1 = Ls @ x,  out = c0*x + c1*T1      (Ls = (2/lub) L - I)
// ---------------------------------------------------------------------------
__global__ void __launch_bounds__(128) cheb_init(const float* __restrict__ X,
                                                 float* __restrict__ out) {
    int row = blockIdx.x;
    __shared__ int   s_col[ELLW];
    __shared__ float s_val[ELLW];
    int cnt = g_cnt[row];
    for (int k = threadIdx.x; k < cnt; k += 128) {
        s_col[k] = g_col[row * ELLW + k];
        s_val[k] = g_val[row * ELLW + k];
    }
    __syncthreads();

    int ch = threadIdx.x << 2;
    size_t ridx = (((size_t)row) << 9) + ch;
    float4 xi = f4_load(X + ridx);
    float d = g_diag[row];

    float ax, ay, az, aw;
    spmv_row(X, ch, s_col, s_val, cnt, d, xi, ax, ay, az, aw);

    float ha = 0.5f * g_a;   // 2/lub
    float4 t1;
    t1.x = ha * ax - xi.x;
    t1.y = ha * ay - xi.y;
    t1.z = ha * az - xi.z;
    t1.w = ha * aw - xi.w;
    f4_store(g_T1 + ridx, t1);

    float c0 = g_coef[0], c1 = g_coef[1];
    float4 o;
    o.x = c0 * xi.x + c1 * t1.x;
    o.y = c0 * xi.y + c1 * t1.y;
    o.z = c0 * xi.z + c1 * t1.z;
    o.w = c0 * xi.w + c1 * t1.w;
    f4_store(out + ridx, o);
}

// ---------------------------------------------------------------------------
// 4) Recurrence step j >= 2:
//    T_j = 2*Ls@T_{j-1} - T_{j-2} = a*(L@T_{j-1}) - 2*T_{j-1} - T_{j-2},
//    out += c_j * T_j.   Ping-pong: odd degrees in g_T1, even in g_T2.
//    T_{j-2} own-row read happens before the T_j own-row write (same thread),
//    so 2 buffers suffice. Kernels beyond the truncation degree early-out.
// ---------------------------------------------------------------------------
__global__ void __launch_bounds__(128) cheb_iter(const float* __restrict__ X,
                                                 float* out, int j) {
    if (j > g_deg) return;
    int row = blockIdx.x;

    const float* Tk   = (j & 1) ? g_T2 : g_T1;   // T_{j-1}
    float*       Tout = (j & 1) ? g_T1 : g_T2;   // T_j (overwrites T_{j-2})
    const float* Tkm1 = (j == 2) ? X : (const float*)Tout;

    __shared__ int   s_col[ELLW];
    __shared__ float s_val[ELLW];
    int cnt = g_cnt[row];
    for (int k = threadIdx.x; k < cnt; k += 128) {
        s_col[k] = g_col[row * ELLW + k];
        s_val[k] = g_val[row * ELLW + k];
    }
    __syncthreads();

    int ch = threadIdx.x << 2;
    size_t ridx = (((size_t)row) << 9) + ch;
    float4 yk   = f4_load(Tk + ridx);
    float4 ykm1 = f4_load(Tkm1 + ridx);   // read before Tout write (same addr ok)
    float d = g_diag[row];

    float ax, ay, az, aw;
    spmv_row(Tk, ch, s_col, s_val, cnt, d, yk, ax, ay, az, aw);

    float a = g_a;  // 4/lub
    float4 tn;
    tn.x = a * ax - 2.f * yk.x - ykm1.x;
    tn.y = a * ay - 2.f * yk.y - ykm1.y;
    tn.z = a * az - 2.f * yk.z - ykm1.z;
    tn.w = a * aw - 2.f * yk.w - ykm1.w;
    f4_store(Tout + ridx, tn);

    float c = g_coef[j];
    float4 o = f4_load(out + ridx);
    o.x += c * tn.x; o.y += c * tn.y; o.z += c * tn.z; o.w += c * tn.w;
    f4_store(out + ridx, o);
}

// ---------------------------------------------------------------------------
extern "C" void kernel_launch(void* const* d_in, const int* in_sizes, int n_in,
                              void* d_out, int out_size) {
    const float* x = nullptr;
    const float* L = nullptr;
    const float* t = nullptr;
    for (int i = 0; i < n_in; i++) {
        if      (in_sizes[i] == NN * DD) x = (const float*)d_in[i];
        else if (in_sizes[i] == NN * NN) L = (const float*)d_in[i];
        else if (in_sizes[i] == 1)       t = (const float*)d_in[i];
    }
    float* out = (float*)d_out;

    prep_kernel<<<NN, 256>>>(L);
    coeff_kernel<<<1, NQ>>>(t);
    cheb_init<<<NN, 128>>>(x, out);
    for (int j = 2; j <= MMAX; j++)
        cheb_iter<<<NN, 128>>>(x, out, j);
}

// round 5
// speedup vs baseline: 1.4081x; 1.4081x over previous
#include <cuda_runtime.h>
#include <math.h>

// Diffusion: out = expm(-max(t,1e-8)*L) @ x, L = graph Laplacian (~32 nnz/row).
// Chebyshev expansion of e^{-t*lambda} on [0, lambda_ub], applied via sparse
// matvecs in fp32, all iterations fused into ONE persistent kernel with a
// software grid barrier (256 blocks, residency guaranteed by launch bounds).

#define NN   2048
#define DD   512
#define ELLW 128          // max off-diag nnz per row (mean ~32)
#define MMAX 48           // highest Chebyshev degree available
#define RPB  8            // rows per block
#define TPR  64           // threads per row (8 channels each)
#define THREADS (RPB*TPR) // 512
#define GRID (NN/RPB)     // 256 blocks  (<= 148 SMs * 2 resident)

// -------- device-global scratch (no allocations allowed) --------
__device__ int   g_cnt[NN];
__device__ float g_diag[NN];
__device__ int   g_col[NN * ELLW];
__device__ float g_val[NN * ELLW];
__device__ float g_coef[MMAX + 1];
__device__ float g_a;     // 4 / lambda_ub
__device__ int   g_deg;   // truncation degree (data dependent)
__device__ float g_T1[NN * DD];
__device__ float g_T2[NN * DD];

// software grid barrier state
__device__ int          g_bar_count = 0;
__device__ volatile int g_bar_gen   = 0;

__device__ __forceinline__ float4 f4_load(const float* p) {
    return *reinterpret_cast<const float4*>(p);
}
__device__ __forceinline__ void f4_store(float* p, float4 v) {
    *reinterpret_cast<float4*>(p) = v;
}

__device__ __forceinline__ void grid_barrier() {
    __threadfence();          // publish this block's stores (all threads)
    __syncthreads();
    if (threadIdx.x == 0) {
        int gen = g_bar_gen;
        if (atomicAdd(&g_bar_count, 1) == GRID - 1) {
            g_bar_count = 0;
            __threadfence();
            g_bar_gen = gen + 1;
        } else {
            while (g_bar_gen == gen) __nanosleep(64);
        }
        __threadfence();      // acquire side
    }
    __syncthreads();
}

// ---------------------------------------------------------------------------
// 1) Extract sparse structure from dense L (one block per row).
// ---------------------------------------------------------------------------
__global__ void __launch_bounds__(256) prep_kernel(const float* __restrict__ L) {
    int row = blockIdx.x;
    int t   = threadIdx.x;
    const float* Lr = L + (size_t)row * NN;

    int   cols[8];
    float vals[8];
    int   cnt  = 0;
    float dval = 0.f;
    int base = t * 8;
#pragma unroll
    for (int k = 0; k < 8; k++) {
        int c = base + k;
        float v = Lr[c];
        if (c == row) {
            dval = v;
        } else if (v != 0.f) {
            cols[cnt] = c;
            vals[cnt] = -v;   // A_ij = -L_ij
            cnt++;
        }
    }

    __shared__ int s_scan[256];
    s_scan[t] = cnt;
    __syncthreads();
    for (int off = 1; off < 256; off <<= 1) {
        int add = (t >= off) ? s_scan[t - off] : 0;
        __syncthreads();
        s_scan[t] += add;
        __syncthreads();
    }
    int offset = s_scan[t] - cnt;
    int total  = s_scan[255];

    for (int k = 0; k < cnt; k++) {
        int idx = offset + k;
        if (idx < ELLW) {
            g_col[row * ELLW + idx] = cols[k];
            g_val[row * ELLW + idx] = vals[k];
        }
    }
    if ((row >> 3) == t) g_diag[row] = dval;
    if (t == 0) g_cnt[row] = (total < ELLW) ? total : ELLW;
}

// ---------------------------------------------------------------------------
// 2) Chebyshev coefficients of exp(-z*(s+1)) via 64-node fp64 DCT, single
//    warp, cos-recurrence. Tail tolerance 2e-5 (measured amplification ~10x,
//    threshold 1e-3 -> 5x margin).
// ---------------------------------------------------------------------------
__global__ void __launch_bounds__(32) coeff_kernel(const float* __restrict__ t_in) {
    int lane = threadIdx.x;

    float m = 0.f;
    for (int i = lane; i < NN; i += 32) m = fmaxf(m, g_diag[i]);
#pragma unroll
    for (int off = 16; off; off >>= 1)
        m = fmaxf(m, __shfl_xor_sync(0xffffffffu, m, off));
    double lub = 2.0 * (double)m;
    if (lub < 1e-12) lub = 1e-12;

    double tt = (double)fmaxf(t_in[0], 1e-8f);
    double z  = 0.5 * tt * lub;

    const double PI = 3.14159265358979323846;
    double th0 = PI * ((double)lane + 0.5) / 64.0;
    double th1 = PI * ((double)(lane + 32) + 0.5) / 64.0;
    double ct0 = cos(th0), ct1 = cos(th1);
    double f0 = exp(-z * (ct0 + 1.0));
    double f1 = exp(-z * (ct1 + 1.0));

    double cm2_0 = 1.0, cm1_0 = ct0, tc0 = 2.0 * ct0;
    double cm2_1 = 1.0, cm1_1 = ct1, tc1 = 2.0 * ct1;

    __shared__ double s_c[MMAX + 1];
    for (int k = 0; k <= MMAX; k++) {
        double ck0, ck1;
        if (k == 0)      { ck0 = 1.0; ck1 = 1.0; }
        else if (k == 1) { ck0 = ct0; ck1 = ct1; }
        else {
            ck0 = tc0 * cm1_0 - cm2_0;  cm2_0 = cm1_0;  cm1_0 = ck0;
            ck1 = tc1 * cm1_1 - cm2_1;  cm2_1 = cm1_1;  cm1_1 = ck1;
        }
        double p = f0 * ck0 + f1 * ck1;
#pragma unroll
        for (int off = 16; off; off >>= 1)
            p += __shfl_xor_sync(0xffffffffu, p, off);
        if (lane == 0) {
            double c = (2.0 / 64.0) * p;
            if (k == 0) c *= 0.5;
            s_c[k] = c;
        }
    }
    __syncwarp();
    if (lane == 0) {
        double tail = 0.0;
        int deg = 2;
        for (int k = MMAX; k >= 2; k--) {
            tail += fabs(s_c[k]);
            if (tail > 2e-5) { deg = k; break; }
        }
        if (deg > MMAX) deg = MMAX;
        g_deg = deg;
        g_a   = (float)(4.0 / lub);
        for (int k = 0; k <= MMAX; k++) g_coef[k] = (float)s_c[k];
    }
}

// ---------------------------------------------------------------------------
// SpMV core: acc[0..7] = d*yk - sum_j val_j * Y[col_j, ch..ch+7]
// unroll-2 -> 4 independent LDG.128 in flight per thread
// ---------------------------------------------------------------------------
__device__ __forceinline__ void spmv8(const float* __restrict__ Y, int ch,
                                      const int* __restrict__ sc,
                                      const float* __restrict__ sv,
                                      int cnt, float d,
                                      const float yk[8], float acc[8]) {
#pragma unroll
    for (int i = 0; i < 8; i++) acc[i] = d * yk[i];
    int k = 0;
    for (; k + 2 <= cnt; k += 2) {
        int   c0 = sc[k],     c1 = sc[k + 1];
        float v0 = sv[k],     v1 = sv[k + 1];
        const float* p0 = Y + (((size_t)c0) << 9) + ch;
        const float* p1 = Y + (((size_t)c1) << 9) + ch;
        float4 a0 = f4_load(p0), a1 = f4_load(p0 + 4);
        float4 b0 = f4_load(p1), b1 = f4_load(p1 + 4);
        acc[0] -= v0 * a0.x; acc[1] -= v0 * a0.y; acc[2] -= v0 * a0.z; acc[3] -= v0 * a0.w;
        acc[4] -= v0 * a1.x; acc[5] -= v0 * a1.y; acc[6] -= v0 * a1.z; acc[7] -= v0 * a1.w;
        acc[0] -= v1 * b0.x; acc[1] -= v1 * b0.y; acc[2] -= v1 * b0.z; acc[3] -= v1 * b0.w;
        acc[4] -= v1 * b1.x; acc[5] -= v1 * b1.y; acc[6] -= v1 * b1.z; acc[7] -= v1 * b1.w;
    }
    if (k < cnt) {
        int   c0 = sc[k];
        float v0 = sv[k];
        const float* p0 = Y + (((size_t)c0) << 9) + ch;
        float4 a0 = f4_load(p0), a1 = f4_load(p0 + 4);
        acc[0] -= v0 * a0.x; acc[1] -= v0 * a0.y; acc[2] -= v0 * a0.z; acc[3] -= v0 * a0.w;
        acc[4] -= v0 * a1.x; acc[5] -= v0 * a1.y; acc[6] -= v0 * a1.z; acc[7] -= v0 * a1.w;
    }
}

// ---------------------------------------------------------------------------
// 3) Persistent Chebyshev kernel: all iterations, grid barrier between them.
//    out accumulator + T_{j-1} own-row in registers, T_{j-2} own-row in smem,
//    ELL lists loaded to smem once. 256 blocks x 512 thr, >=2 blocks/SM
//    guaranteed -> single wave -> barrier is deadlock-free.
// ---------------------------------------------------------------------------
__global__ void __launch_bounds__(THREADS, 2)
cheb_persist(const float* __restrict__ X, float* __restrict__ out) {
    const int rl   = threadIdx.x >> 6;       // row within block (0..7)
    const int lane = threadIdx.x & 63;
    const int row  = blockIdx.x * RPB + rl;

    __shared__ int   s_col[RPB][ELLW];
    __shared__ float s_val[RPB][ELLW];
    __shared__ float s_ykm1[RPB][TPR * 8];
    __shared__ float s_coef[MMAX + 1];

    const int cnt = g_cnt[row];
    for (int k = lane; k < cnt; k += TPR) {
        s_col[rl][k] = g_col[row * ELLW + k];
        s_val[rl][k] = g_val[row * ELLW + k];
    }
    if (threadIdx.x <= MMAX) s_coef[threadIdx.x] = g_coef[threadIdx.x];
    __syncthreads();

    const float d   = g_diag[row];
    const float a   = g_a;        // 4/lub
    const int   deg = g_deg;
    const int   ch  = lane << 3;
    const size_t ridx = (((size_t)row) << 9) + ch;

    float yk[8], acc[8], o[8];
    {
        float4 xa = f4_load(X + ridx), xb = f4_load(X + ridx + 4);
        yk[0] = xa.x; yk[1] = xa.y; yk[2] = xa.z; yk[3] = xa.w;
        yk[4] = xb.x; yk[5] = xb.y; yk[6] = xb.z; yk[7] = xb.w;
    }

    // T1 = (2/lub)*L@x - x ;  out = c0*x + c1*T1
    spmv8(X, ch, s_col[rl], s_val[rl], cnt, d, yk, acc);
    {
        const float ha = 0.5f * a;
        const float c0 = s_coef[0], c1 = s_coef[1];
#pragma unroll
        for (int i = 0; i < 8; i++) {
            float t1 = ha * acc[i] - yk[i];
            o[i] = c0 * yk[i] + c1 * t1;
            s_ykm1[rl][ch + i] = yk[i];   // T0
            yk[i] = t1;                   // T1
        }
        float4 va = {yk[0], yk[1], yk[2], yk[3]};
        float4 vb = {yk[4], yk[5], yk[6], yk[7]};
        f4_store(g_T1 + ridx, va);
        f4_store(g_T1 + ridx + 4, vb);
    }

    for (int j = 2; j <= deg; j++) {
        grid_barrier();                       // T_{j-1} globally visible
        const float* Tp = (j & 1) ? g_T2 : g_T1;
        float*       Tc = (j & 1) ? g_T1 : g_T2;

        spmv8(Tp, ch, s_col[rl], s_val[rl], cnt, d, yk, acc);

        const float c = s_coef[j];
        float tn[8];
#pragma unroll
        for (int i = 0; i < 8; i++) {
            tn[i] = a * acc[i] - 2.f * yk[i] - s_ykm1[rl][ch + i];
            o[i] += c * tn[i];
            s_ykm1[rl][ch + i] = yk[i];
            yk[i] = tn[i];
        }
        if (j < deg) {                        // last T never gathered
            float4 va = {tn[0], tn[1], tn[2], tn[3]};
            float4 vb = {tn[4], tn[5], tn[6], tn[7]};
            f4_store(Tc + ridx, va);
            f4_store(Tc + ridx + 4, vb);
        }
    }

    float4 oa = {o[0], o[1], o[2], o[3]};
    float4 ob = {o[4], o[5], o[6], o[7]};
    f4_store(out + ridx, oa);
    f4_store(out + ridx + 4, ob);
}

// ---------------------------------------------------------------------------
extern "C" void kernel_launch(void* const* d_in, const int* in_sizes, int n_in,
                              void* d_out, int out_size) {
    const float* x = nullptr;
    const float* L = nullptr;
    const float* t = nullptr;
    for (int i = 0; i < n_in; i++) {
        if      (in_sizes[i] == NN * DD) x = (const float*)d_in[i];
        else if (in_sizes[i] == NN * NN) L = (const float*)d_in[i];
        else if (in_sizes[i] == 1)       t = (const float*)d_in[i];
    }
    float* out = (float*)d_out;

    prep_kernel<<<NN, 256>>>(L);
    coeff_kernel<<<1, 32>>>(t);
    cheb_persist<<<GRID, THREADS>>>(x, out);
}